// round 5
// baseline (speedup 1.0000x reference)
#include <cuda_runtime.h>
#include <cuda_bf16.h>

// Problem constants (fixed shapes for KipfAndWillingConv_24464133718385)
#define N_NODES   100000
#define NFEAT     128
#define MAX_NODES 100000

// Scratch for XF = x @ filters (51.2 MB). __device__ global (no allocs allowed).
// __align__(16): we issue LDG.E.128 / STG.E.128 against this symbol.
__device__ __align__(16) float g_XF[MAX_NODES * NFEAT];

// ---------------------------------------------------------------------------
// Kernel 1: zero the output (harness poisons d_out with 0xAA before timing)
// ---------------------------------------------------------------------------
__global__ void zero_out_kernel(float4* __restrict__ out, int n4) {
    int i = blockIdx.x * blockDim.x + threadIdx.x;
    int stride = gridDim.x * blockDim.x;
    float4 z = make_float4(0.f, 0.f, 0.f, 0.f);
    for (; i < n4; i += stride) out[i] = z;
}

// ---------------------------------------------------------------------------
// Kernel 2: XF = x @ F   (x: [n,128], F: [128,128], row-major)
// Block: 256 threads. Tile: 64 rows x 128 cols, full K=128.
// Static shared: 64 x 132 floats (33 KB, padded stride -> conflict-free LDS:
//   bank(row,k) = (4*row + k) mod 32, distinct rows hit distinct banks).
// Thread computes 4 rows x 8 cols. F streamed through L1 (64KB, resident).
// ---------------------------------------------------------------------------
#define XS_STRIDE 132

__global__ void gemm_xf_kernel(const float* __restrict__ x,
                               const float* __restrict__ f,
                               int n) {
    __shared__ float xs[64 * XS_STRIDE];   // 33792 B static

    const int tid      = threadIdx.x;
    const int blockRow = blockIdx.x * 64;
    const int col0     = (tid & 15) * 8;   // 16 col-groups * 8 cols
    const int row0     = (tid >> 4) * 4;   // 16 row-groups * 4 rows

    // Cooperative load of the 64x128 x tile (float4 loads, scalar smem stores
    // into the padded layout).
    const float4* x4 = (const float4*)x;
    #pragma unroll
    for (int i = tid; i < 64 * 32; i += 256) {
        int r  = i >> 5;            // row within tile
        int c4 = i & 31;            // float4 column
        int gr = blockRow + r;
        float4 v = (gr < n) ? __ldg(&x4[gr * 32 + c4])
                            : make_float4(0.f, 0.f, 0.f, 0.f);
        float* dstp = &xs[r * XS_STRIDE + c4 * 4];
        dstp[0] = v.x; dstp[1] = v.y; dstp[2] = v.z; dstp[3] = v.w;
    }
    __syncthreads();

    float acc[4][8];
    #pragma unroll
    for (int i = 0; i < 4; i++)
        #pragma unroll
        for (int j = 0; j < 8; j++) acc[i][j] = 0.f;

    const float4* f4 = (const float4*)f;
    const int cg = col0 >> 2;  // float4 index of col0

    #pragma unroll 4
    for (int k = 0; k < 128; k++) {
        float4 b0 = __ldg(&f4[k * 32 + cg]);
        float4 b1 = __ldg(&f4[k * 32 + cg + 1]);
        float bb[8] = {b0.x, b0.y, b0.z, b0.w, b1.x, b1.y, b1.z, b1.w};
        #pragma unroll
        for (int i = 0; i < 4; i++) {
            float a = xs[(row0 + i) * XS_STRIDE + k];
            #pragma unroll
            for (int j = 0; j < 8; j++) acc[i][j] += a * bb[j];
        }
    }

    // Store 4 rows x 8 cols as 2 float4 per row
    #pragma unroll
    for (int i = 0; i < 4; i++) {
        int gr = blockRow + row0 + i;
        if (gr < n) {
            float4* dst = (float4*)&g_XF[gr * NFEAT + col0];
            dst[0] = make_float4(acc[i][0], acc[i][1], acc[i][2], acc[i][3]);
            dst[1] = make_float4(acc[i][4], acc[i][5], acc[i][6], acc[i][7]);
        }
    }
}

// ---------------------------------------------------------------------------
// Kernel 3: segment aggregation over sorted edge_dst (edges are INT32).
// Block: 256 threads = 8 warps, stages 2048 edges (src/dst/w) in smem.
// Each warp owns a contiguous 256-edge sub-range; lane l owns features
// [4l, 4l+4): each edge's gather is ONE coalesced 128B LDG per warp.
// Segment accumulation in float4 registers; flush with atomicAdd only at
// dst-change boundaries (sorted dst => ~1 flush per ~32 edges average).
// Unsigned bounds guards: invalid indices are skipped instead of trapping.
// ---------------------------------------------------------------------------
#define EPB 2048   // edges per block
#define EPW 256    // edges per warp (EPB / 8 warps)

__global__ void aggregate_kernel(const int* __restrict__ src,
                                 const int* __restrict__ dst,
                                 const float* __restrict__ w,
                                 float* __restrict__ out,
                                 int E, int n) {
    __shared__ int   s_src[EPB];
    __shared__ int   s_dst[EPB];
    __shared__ float s_w[EPB];

    const int tid  = threadIdx.x;
    const long long base = (long long)blockIdx.x * EPB;

    // Cooperative staging (coalesced int32/float loads)
    for (int i = tid; i < EPB; i += 256) {
        long long e = base + i;
        if (e < E) {
            s_src[i] = src[e];
            s_dst[i] = dst[e];
            s_w[i]   = w[e];
        } else {
            s_src[i] = 0;
            s_dst[i] = -1;
            s_w[i]   = 0.f;
        }
    }
    __syncthreads();

    const int warp = tid >> 5;
    const int lane = tid & 31;
    const int i0   = warp * EPW;

    long long gbase = base + i0;
    if (gbase >= E) return;
    int cnt = EPW;
    if (gbase + EPW > E) cnt = (int)(E - gbase);

    const float4* xf4 = (const float4*)g_XF;
    const unsigned un = (unsigned)n;

    float4 acc = make_float4(0.f, 0.f, 0.f, 0.f);
    int prev = s_dst[i0];

    #pragma unroll 4
    for (int i = 0; i < cnt; i++) {
        const int idx  = i0 + i;
        const int s    = s_src[idx];
        const int d    = s_dst[idx];
        const float wv = s_w[idx];

        if (d != prev) {                         // warp-uniform branch
            if ((unsigned)prev < un) {
                float* p = &out[prev * NFEAT + lane * 4];
                atomicAdd(p + 0, acc.x);
                atomicAdd(p + 1, acc.y);
                atomicAdd(p + 2, acc.z);
                atomicAdd(p + 3, acc.w);
            }
            acc = make_float4(0.f, 0.f, 0.f, 0.f);
            prev = d;
        }
        if ((unsigned)s < un) {
            float4 v = __ldg(&xf4[s * 32 + lane]);   // 128B coalesced per warp
            acc.x += wv * v.x;
            acc.y += wv * v.y;
            acc.z += wv * v.z;
            acc.w += wv * v.w;
        }
    }
    // Final flush
    if ((unsigned)prev < un) {
        float* p = &out[prev * NFEAT + lane * 4];
        atomicAdd(p + 0, acc.x);
        atomicAdd(p + 1, acc.y);
        atomicAdd(p + 2, acc.z);
        atomicAdd(p + 3, acc.w);
    }
}

// ---------------------------------------------------------------------------
// Launch (kernel launches only — graph-capturable, no host API calls)
// ---------------------------------------------------------------------------
extern "C" void kernel_launch(void* const* d_in, const int* in_sizes, int n_in,
                              void* d_out, int out_size) {
    const float* x    = (const float*)d_in[0];   // [n, 128] fp32
    const float* filt = (const float*)d_in[1];   // [128, 128] fp32
    const int*   src  = (const int*)d_in[2];     // [E] int32 (JAX x64 disabled)
    const int*   dst  = (const int*)d_in[3];     // [E] int32, sorted
    const float* w    = (const float*)d_in[4];   // [E] fp32
    float*       out  = (float*)d_out;           // [n, 128] fp32

    const int n = in_sizes[0] / NFEAT;   // 100000
    const int E = in_sizes[2];           // 3200000

    // Zero output (poisoned 0xAA by harness)
    int n4 = out_size / 4;
    zero_out_kernel<<<2048, 256>>>((float4*)out, n4);

    // GEMM: XF = x @ F  (static smem, no attribute calls)
    int gemm_blocks = (n + 63) / 64;
    gemm_xf_kernel<<<gemm_blocks, 256>>>(x, filt, n);

    // Sorted-segment aggregation (int32 edge indices)
    int agg_blocks = (E + EPB - 1) / EPB;
    aggregate_kernel<<<agg_blocks, 256>>>(src, dst, w, out, E, n);
}

// round 7
// speedup vs baseline: 1.4015x; 1.4015x over previous
#include <cuda_runtime.h>
#include <cuda_bf16.h>
#include <cstdint>

// Problem constants (fixed shapes for KipfAndWillingConv_24464133718385)
#define NFEAT     128
#define MAX_NODES 100000

// Scratch (no allocs allowed -> __device__ globals)
__device__ __align__(16) float g_XF[MAX_NODES * NFEAT];          // x @ F
__device__ __align__(16) __nv_bfloat16 g_Fhi[NFEAT * NFEAT];     // F^T hi, [N][K]
__device__ __align__(16) __nv_bfloat16 g_Flo[NFEAT * NFEAT];     // F^T lo, [N][K]

__device__ __forceinline__ uint32_t smem_u32(const void* p) {
    uint32_t a;
    asm("{ .reg .u64 t; cvta.to.shared.u64 t, %1; cvt.u32.u64 %0, t; }"
        : "=r"(a) : "l"(p));
    return a;
}

// Split a float2 into packed bf16x2 hi and bf16x2 lo(residual).
// Low 16 bits of each word = first element (lower column index).
__device__ __forceinline__ void split2(float2 v, uint32_t& hi, uint32_t& lo) {
    __nv_bfloat162 h2 = __floats2bfloat162_rn(v.x, v.y);
    uint32_t h = *reinterpret_cast<uint32_t*>(&h2);
    float rx = v.x - __uint_as_float(h << 16);
    float ry = v.y - __uint_as_float(h & 0xffff0000u);
    __nv_bfloat162 l2 = __floats2bfloat162_rn(rx, ry);
    hi = h;
    lo = *reinterpret_cast<uint32_t*>(&l2);
}

__device__ __forceinline__ float2 ldx_guard(const float* __restrict__ x,
                                            int row, int col, int n) {
    if (row < n) return *(const float2*)(x + (size_t)row * NFEAT + col);
    return make_float2(0.f, 0.f);
}

#define MMA16816(c, a0, a1, a2, a3, b0, b1)                                      \
    asm volatile(                                                                \
        "mma.sync.aligned.m16n8k16.row.col.f32.bf16.bf16.f32 "                   \
        "{%0,%1,%2,%3}, {%4,%5,%6,%7}, {%8,%9}, {%0,%1,%2,%3};"                  \
        : "+f"((c)[0]), "+f"((c)[1]), "+f"((c)[2]), "+f"((c)[3])                 \
        : "r"(a0), "r"(a1), "r"(a2), "r"(a3), "r"(b0), "r"(b1))

#define LDMATRIX_X4(r0, r1, r2, r3, addr)                                        \
    asm volatile("ldmatrix.sync.aligned.m8n8.x4.shared.b16 {%0,%1,%2,%3}, [%4];" \
                 : "=r"(r0), "=r"(r1), "=r"(r2), "=r"(r3) : "r"(addr))

// ---------------------------------------------------------------------------
// Kernel 1: prep — zero the output AND build bf16 hi/lo split of F^T.
// F is [K=128, N=128] row-major; store [N][K] (K-major) = col-major B for mma.
// ---------------------------------------------------------------------------
__global__ void prep_kernel(const float* __restrict__ filt,
                            float4* __restrict__ out, int n4) {
    int i = blockIdx.x * blockDim.x + threadIdx.x;
    if (i < NFEAT * NFEAT) {
        int k = i >> 7, nn = i & 127;           // filt[k][nn]
        float v = filt[i];
        __nv_bfloat16 hi = __float2bfloat16(v);
        float rem = v - __bfloat162float(hi);
        g_Fhi[nn * NFEAT + k] = hi;
        g_Flo[nn * NFEAT + k] = __float2bfloat16(rem);
    }
    float4 z = make_float4(0.f, 0.f, 0.f, 0.f);
    int stride = gridDim.x * blockDim.x;
    for (int j = i; j < n4; j += stride) out[j] = z;
}

// ---------------------------------------------------------------------------
// Kernel 2: bf16 mma.sync GEMM, 3-term split (hi*hi + lo*hi + hi*lo).
// Block: 256 threads (8 warps, 4x2), tile 128 rows x 64 cols; grid.y = N-half.
// B^T (hi/lo) in smem: [64 n][136 k] bf16 each (272B row stride ->
// ldmatrix conflict-free; 16B-aligned k-offsets). A fragments loaded straight
// from global x (guarded float2) and split to bf16 hi/lo in registers.
// ---------------------------------------------------------------------------
#define BROW 68   // words per B smem row (136 bf16)

__global__ void __launch_bounds__(256, 2)
gemm_mma_kernel(const float* __restrict__ x, int n) {
    __shared__ __align__(16) uint32_t sBhi[64 * BROW];   // 17408 B
    __shared__ __align__(16) uint32_t sBlo[64 * BROW];   // 17408 B

    const int tid   = threadIdx.x;
    const int lane  = tid & 31;
    const int warp  = tid >> 5;
    const int warpR = warp >> 1;          // 0..3 -> 32-row band
    const int warpC = warp & 1;           // 0..1 -> 32-col band
    const int grp   = lane >> 2;          // 0..7
    const int tig   = lane & 3;           // 0..3
    const int rowBase = blockIdx.x * 128;
    const int n0      = blockIdx.y * 64;

    // Fill B smem (g_F* rows are 128 bf16 = 64 words; dst stride 68 words)
    {
        const uint32_t* fh = (const uint32_t*)g_Fhi;
        const uint32_t* fl = (const uint32_t*)g_Flo;
        #pragma unroll 4
        for (int i = tid; i < 64 * 64; i += 256) {
            int nr = i >> 6, kw = i & 63;
            sBhi[nr * BROW + kw] = fh[(n0 + nr) * 64 + kw];
            sBlo[nr * BROW + kw] = fl[(n0 + nr) * 64 + kw];
        }
    }
    __syncthreads();

    const uint32_t sBhi_u = smem_u32(sBhi);
    const uint32_t sBlo_u = smem_u32(sBlo);

    float acc[2][4][4];
    #pragma unroll
    for (int i = 0; i < 2; i++)
        #pragma unroll
        for (int j = 0; j < 4; j++)
            #pragma unroll
            for (int q = 0; q < 4; q++) acc[i][j][q] = 0.f;

    // ldmatrix lane-role (constant across k-steps)
    const int sub = lane >> 3;            // which 8x8 matrix this lane feeds
    const int t8  = lane & 7;
    const int nl_base = warpC * 32 + ((sub >> 1) << 3) + t8;  // + p*16
    const int kc_off  = (sub & 1) << 3;                        // +0 or +8

    #pragma unroll
    for (int ks = 0; ks < 8; ks++) {
        const int k0 = ks << 4;

        // B fragments: 4 n-tiles (2 ldmatrix.x4 each for hi and lo)
        uint32_t bh[8], bl[8];
        #pragma unroll
        for (int p = 0; p < 2; p++) {
            uint32_t off = (uint32_t)((nl_base + p * 16) * 272 + (k0 + kc_off) * 2);
            LDMATRIX_X4(bh[4 * p + 0], bh[4 * p + 1], bh[4 * p + 2], bh[4 * p + 3],
                        sBhi_u + off);
            LDMATRIX_X4(bl[4 * p + 0], bl[4 * p + 1], bl[4 * p + 2], bl[4 * p + 3],
                        sBlo_u + off);
        }

        // A fragments from global + mma
        #pragma unroll
        for (int i = 0; i < 2; i++) {
            const int ra = rowBase + warpR * 32 + 16 * i + grp;
            const int rb = ra + 8;
            const int c0 = k0 + 2 * tig;
            const int c1 = c0 + 8;
            float2 v0 = ldx_guard(x, ra, c0, n);
            float2 v1 = ldx_guard(x, rb, c0, n);
            float2 v2 = ldx_guard(x, ra, c1, n);
            float2 v3 = ldx_guard(x, rb, c1, n);
            uint32_t ah[4], al[4];
            split2(v0, ah[0], al[0]);
            split2(v1, ah[1], al[1]);
            split2(v2, ah[2], al[2]);
            split2(v3, ah[3], al[3]);

            #pragma unroll
            for (int j = 0; j < 4; j++) {
                float* c = acc[i][j];
                MMA16816(c, ah[0], ah[1], ah[2], ah[3], bh[2 * j], bh[2 * j + 1]);
                MMA16816(c, al[0], al[1], al[2], al[3], bh[2 * j], bh[2 * j + 1]);
                MMA16816(c, ah[0], ah[1], ah[2], ah[3], bl[2 * j], bl[2 * j + 1]);
            }
        }
    }

    // Epilogue: c0,c1 -> (row, col..col+1); c2,c3 -> (row+8, ...)
    #pragma unroll
    for (int i = 0; i < 2; i++) {
        const int ra = rowBase + warpR * 32 + 16 * i + grp;
        #pragma unroll
        for (int j = 0; j < 4; j++) {
            const int col = n0 + warpC * 32 + 8 * j + 2 * tig;
            if (ra < n)
                *(float2*)&g_XF[(size_t)ra * NFEAT + col] =
                    make_float2(acc[i][j][0], acc[i][j][1]);
            if (ra + 8 < n)
                *(float2*)&g_XF[(size_t)(ra + 8) * NFEAT + col] =
                    make_float2(acc[i][j][2], acc[i][j][3]);
        }
    }
}

// ---------------------------------------------------------------------------
// Kernel 3: segment aggregation over sorted edge_dst (int32 edges).
// Warp owns 256 contiguous edges; lane l owns features [4l,4l+4):
// one coalesced 128B LDG per edge per warp; register accumulation with
// atomic flush only at dst-change boundaries. (Unchanged from R5 — proven.)
// ---------------------------------------------------------------------------
#define EPB 2048
#define EPW 256

__global__ void aggregate_kernel(const int* __restrict__ src,
                                 const int* __restrict__ dst,
                                 const float* __restrict__ w,
                                 float* __restrict__ out,
                                 int E, int n) {
    __shared__ int   s_src[EPB];
    __shared__ int   s_dst[EPB];
    __shared__ float s_w[EPB];

    const int tid  = threadIdx.x;
    const long long base = (long long)blockIdx.x * EPB;

    for (int i = tid; i < EPB; i += 256) {
        long long e = base + i;
        if (e < E) {
            s_src[i] = src[e];
            s_dst[i] = dst[e];
            s_w[i]   = w[e];
        } else {
            s_src[i] = 0;
            s_dst[i] = -1;
            s_w[i]   = 0.f;
        }
    }
    __syncthreads();

    const int warp = tid >> 5;
    const int lane = tid & 31;
    const int i0   = warp * EPW;

    long long gbase = base + i0;
    if (gbase >= E) return;
    int cnt = EPW;
    if (gbase + EPW > E) cnt = (int)(E - gbase);

    const float4* xf4 = (const float4*)g_XF;
    const unsigned un = (unsigned)n;

    float4 acc = make_float4(0.f, 0.f, 0.f, 0.f);
    int prev = s_dst[i0];

    #pragma unroll 4
    for (int i = 0; i < cnt; i++) {
        const int idx  = i0 + i;
        const int s    = s_src[idx];
        const int d    = s_dst[idx];
        const float wv = s_w[idx];

        if (d != prev) {                         // warp-uniform branch
            if ((unsigned)prev < un) {
                float* p = &out[prev * NFEAT + lane * 4];
                atomicAdd(p + 0, acc.x);
                atomicAdd(p + 1, acc.y);
                atomicAdd(p + 2, acc.z);
                atomicAdd(p + 3, acc.w);
            }
            acc = make_float4(0.f, 0.f, 0.f, 0.f);
            prev = d;
        }
        if ((unsigned)s < un) {
            float4 v = __ldg(&xf4[s * 32 + lane]);   // 128B coalesced per warp
            acc.x += wv * v.x;
            acc.y += wv * v.y;
            acc.z += wv * v.z;
            acc.w += wv * v.w;
        }
    }
    if ((unsigned)prev < un) {
        float* p = &out[prev * NFEAT + lane * 4];
        atomicAdd(p + 0, acc.x);
        atomicAdd(p + 1, acc.y);
        atomicAdd(p + 2, acc.z);
        atomicAdd(p + 3, acc.w);
    }
}

// ---------------------------------------------------------------------------
// Launch (kernel launches only — graph-capturable)
// ---------------------------------------------------------------------------
extern "C" void kernel_launch(void* const* d_in, const int* in_sizes, int n_in,
                              void* d_out, int out_size) {
    const float* x    = (const float*)d_in[0];   // [n, 128] fp32
    const float* filt = (const float*)d_in[1];   // [128, 128] fp32
    const int*   src  = (const int*)d_in[2];     // [E] int32
    const int*   dst  = (const int*)d_in[3];     // [E] int32, sorted
    const float* w    = (const float*)d_in[4];   // [E] fp32
    float*       out  = (float*)d_out;           // [n, 128] fp32

    const int n = in_sizes[0] / NFEAT;   // 100000
    const int E = in_sizes[2];           // 3200000

    // Prep: zero out + split filters into bf16 hi/lo (transposed)
    prep_kernel<<<2048, 256>>>(filt, (float4*)out, out_size / 4);

    // GEMM: XF = x @ F via mma.sync bf16 3-term split
    dim3 ggrid((n + 127) / 128, 2);
    gemm_mma_kernel<<<ggrid, 256>>>(x, n);

    // Sorted-segment aggregation
    int agg_blocks = (E + EPB - 1) / EPB;
    aggregate_kernel<<<agg_blocks, 256>>>(src, dst, w, out, E, n);
}

// round 8
// speedup vs baseline: 1.6882x; 1.2045x over previous
#include <cuda_runtime.h>
#include <cuda_bf16.h>
#include <cuda_fp16.h>
#include <cstdint>

// Problem constants (fixed shapes for KipfAndWillingConv_24464133718385)
#define NFEAT     128
#define MAX_NODES 100000

// Scratch (no allocs allowed -> __device__ globals)
// XF stored in FP16 (25.6 MB): halves gather traffic in the L2-bound
// aggregation; norm-relative error contribution ~2.8e-4 << 1e-3 gate.
__device__ __align__(16) __half g_XF[MAX_NODES * NFEAT];         // x @ F (fp16)
__device__ __align__(16) __nv_bfloat16 g_Fhi[NFEAT * NFEAT];     // F^T hi, [N][K]
__device__ __align__(16) __nv_bfloat16 g_Flo[NFEAT * NFEAT];     // F^T lo, [N][K]

__device__ __forceinline__ uint32_t smem_u32(const void* p) {
    uint32_t a;
    asm("{ .reg .u64 t; cvta.to.shared.u64 t, %1; cvt.u32.u64 %0, t; }"
        : "=r"(a) : "l"(p));
    return a;
}

// Split a float2 into packed bf16x2 hi and bf16x2 lo(residual).
// Low 16 bits of each word = first element (lower column index).
__device__ __forceinline__ void split2(float2 v, uint32_t& hi, uint32_t& lo) {
    __nv_bfloat162 h2 = __floats2bfloat162_rn(v.x, v.y);
    uint32_t h = *reinterpret_cast<uint32_t*>(&h2);
    float rx = v.x - __uint_as_float(h << 16);
    float ry = v.y - __uint_as_float(h & 0xffff0000u);
    __nv_bfloat162 l2 = __floats2bfloat162_rn(rx, ry);
    hi = h;
    lo = *reinterpret_cast<uint32_t*>(&l2);
}

__device__ __forceinline__ float2 ldx_guard(const float* __restrict__ x,
                                            int row, int col, int n) {
    if (row < n) return *(const float2*)(x + (size_t)row * NFEAT + col);
    return make_float2(0.f, 0.f);
}

#define MMA16816(c, a0, a1, a2, a3, b0, b1)                                      \
    asm volatile(                                                                \
        "mma.sync.aligned.m16n8k16.row.col.f32.bf16.bf16.f32 "                   \
        "{%0,%1,%2,%3}, {%4,%5,%6,%7}, {%8,%9}, {%0,%1,%2,%3};"                  \
        : "+f"((c)[0]), "+f"((c)[1]), "+f"((c)[2]), "+f"((c)[3])                 \
        : "r"(a0), "r"(a1), "r"(a2), "r"(a3), "r"(b0), "r"(b1))

#define LDMATRIX_X4(r0, r1, r2, r3, addr)                                        \
    asm volatile("ldmatrix.sync.aligned.m8n8.x4.shared.b16 {%0,%1,%2,%3}, [%4];" \
                 : "=r"(r0), "=r"(r1), "=r"(r2), "=r"(r3) : "r"(addr))

// ---------------------------------------------------------------------------
// Kernel 1: prep — zero the output AND build bf16 hi/lo split of F^T.
// F is [K=128, N=128] row-major; store [N][K] (K-major) = col-major B for mma.
// ---------------------------------------------------------------------------
__global__ void prep_kernel(const float* __restrict__ filt,
                            float4* __restrict__ out, int n4) {
    int i = blockIdx.x * blockDim.x + threadIdx.x;
    if (i < NFEAT * NFEAT) {
        int k = i >> 7, nn = i & 127;           // filt[k][nn]
        float v = filt[i];
        __nv_bfloat16 hi = __float2bfloat16(v);
        float rem = v - __bfloat162float(hi);
        g_Fhi[nn * NFEAT + k] = hi;
        g_Flo[nn * NFEAT + k] = __float2bfloat16(rem);
    }
    float4 z = make_float4(0.f, 0.f, 0.f, 0.f);
    int stride = gridDim.x * blockDim.x;
    for (int j = i; j < n4; j += stride) out[j] = z;
}

// ---------------------------------------------------------------------------
// Kernel 2: bf16 mma.sync GEMM, 3-term split (hi*hi + lo*hi + hi*lo).
// Block: 256 threads (8 warps, 4x2), tile 128 rows x 64 cols; grid.y = N-half.
// B^T (hi/lo) in smem: [64 n][136 k] bf16 each (272B row stride ->
// ldmatrix conflict-free). A fragments loaded straight from global x
// (guarded float2) and split to bf16 hi/lo in registers.
// Epilogue writes XF in fp16 (half2 packs).
// ---------------------------------------------------------------------------
#define BROW 68   // words per B smem row (136 bf16)

__global__ void __launch_bounds__(256, 2)
gemm_mma_kernel(const float* __restrict__ x, int n) {
    __shared__ __align__(16) uint32_t sBhi[64 * BROW];   // 17408 B
    __shared__ __align__(16) uint32_t sBlo[64 * BROW];   // 17408 B

    const int tid   = threadIdx.x;
    const int lane  = tid & 31;
    const int warp  = tid >> 5;
    const int warpR = warp >> 1;          // 0..3 -> 32-row band
    const int warpC = warp & 1;           // 0..1 -> 32-col band
    const int grp   = lane >> 2;          // 0..7
    const int tig   = lane & 3;           // 0..3
    const int rowBase = blockIdx.x * 128;
    const int n0      = blockIdx.y * 64;

    // Fill B smem (g_F* rows are 128 bf16 = 64 words; dst stride 68 words)
    {
        const uint32_t* fh = (const uint32_t*)g_Fhi;
        const uint32_t* fl = (const uint32_t*)g_Flo;
        #pragma unroll 4
        for (int i = tid; i < 64 * 64; i += 256) {
            int nr = i >> 6, kw = i & 63;
            sBhi[nr * BROW + kw] = fh[(n0 + nr) * 64 + kw];
            sBlo[nr * BROW + kw] = fl[(n0 + nr) * 64 + kw];
        }
    }
    __syncthreads();

    const uint32_t sBhi_u = smem_u32(sBhi);
    const uint32_t sBlo_u = smem_u32(sBlo);

    float acc[2][4][4];
    #pragma unroll
    for (int i = 0; i < 2; i++)
        #pragma unroll
        for (int j = 0; j < 4; j++)
            #pragma unroll
            for (int q = 0; q < 4; q++) acc[i][j][q] = 0.f;

    // ldmatrix lane-role (constant across k-steps)
    const int sub = lane >> 3;            // which 8x8 matrix this lane feeds
    const int t8  = lane & 7;
    const int nl_base = warpC * 32 + ((sub >> 1) << 3) + t8;  // + p*16
    const int kc_off  = (sub & 1) << 3;                        // +0 or +8

    #pragma unroll
    for (int ks = 0; ks < 8; ks++) {
        const int k0 = ks << 4;

        // B fragments: 4 n-tiles (2 ldmatrix.x4 each for hi and lo)
        uint32_t bh[8], bl[8];
        #pragma unroll
        for (int p = 0; p < 2; p++) {
            uint32_t off = (uint32_t)((nl_base + p * 16) * 272 + (k0 + kc_off) * 2);
            LDMATRIX_X4(bh[4 * p + 0], bh[4 * p + 1], bh[4 * p + 2], bh[4 * p + 3],
                        sBhi_u + off);
            LDMATRIX_X4(bl[4 * p + 0], bl[4 * p + 1], bl[4 * p + 2], bl[4 * p + 3],
                        sBlo_u + off);
        }

        // A fragments from global + mma
        #pragma unroll
        for (int i = 0; i < 2; i++) {
            const int ra = rowBase + warpR * 32 + 16 * i + grp;
            const int rb = ra + 8;
            const int c0 = k0 + 2 * tig;
            const int c1 = c0 + 8;
            float2 v0 = ldx_guard(x, ra, c0, n);
            float2 v1 = ldx_guard(x, rb, c0, n);
            float2 v2 = ldx_guard(x, ra, c1, n);
            float2 v3 = ldx_guard(x, rb, c1, n);
            uint32_t ah[4], al[4];
            split2(v0, ah[0], al[0]);
            split2(v1, ah[1], al[1]);
            split2(v2, ah[2], al[2]);
            split2(v3, ah[3], al[3]);

            #pragma unroll
            for (int j = 0; j < 4; j++) {
                float* c = acc[i][j];
                MMA16816(c, ah[0], ah[1], ah[2], ah[3], bh[2 * j], bh[2 * j + 1]);
                MMA16816(c, al[0], al[1], al[2], al[3], bh[2 * j], bh[2 * j + 1]);
                MMA16816(c, ah[0], ah[1], ah[2], ah[3], bl[2 * j], bl[2 * j + 1]);
            }
        }
    }

    // Epilogue (fp16): c0,c1 -> (row, col..col+1); c2,c3 -> (row+8, ...)
    #pragma unroll
    for (int i = 0; i < 2; i++) {
        const int ra = rowBase + warpR * 32 + 16 * i + grp;
        #pragma unroll
        for (int j = 0; j < 4; j++) {
            const int col = n0 + warpC * 32 + 8 * j + 2 * tig;
            if (ra < n) {
                __half2 p = __floats2half2_rn(acc[i][j][0], acc[i][j][1]);
                *(uint32_t*)&g_XF[(size_t)ra * NFEAT + col] =
                    *reinterpret_cast<uint32_t*>(&p);
            }
            if (ra + 8 < n) {
                __half2 p = __floats2half2_rn(acc[i][j][2], acc[i][j][3]);
                *(uint32_t*)&g_XF[(size_t)(ra + 8) * NFEAT + col] =
                    *reinterpret_cast<uint32_t*>(&p);
            }
        }
    }
}

// ---------------------------------------------------------------------------
// Kernel 3: segment aggregation over sorted edge_dst (int32 edges).
// Warp owns 256 contiguous edges; lane l owns features [4l,4l+4):
// one coalesced 256B (fp16) access per edge per warp (lane loads 8B uint2).
// fp32 register accumulation; atomic flush only at dst-change boundaries.
// ---------------------------------------------------------------------------
#define EPB 2048
#define EPW 256

__global__ void aggregate_kernel(const int* __restrict__ src,
                                 const int* __restrict__ dst,
                                 const float* __restrict__ w,
                                 float* __restrict__ out,
                                 int E, int n) {
    __shared__ int   s_src[EPB];
    __shared__ int   s_dst[EPB];
    __shared__ float s_w[EPB];

    const int tid  = threadIdx.x;
    const long long base = (long long)blockIdx.x * EPB;

    for (int i = tid; i < EPB; i += 256) {
        long long e = base + i;
        if (e < E) {
            s_src[i] = src[e];
            s_dst[i] = dst[e];
            s_w[i]   = w[e];
        } else {
            s_src[i] = 0;
            s_dst[i] = -1;
            s_w[i]   = 0.f;
        }
    }
    __syncthreads();

    const int warp = tid >> 5;
    const int lane = tid & 31;
    const int i0   = warp * EPW;

    long long gbase = base + i0;
    if (gbase >= E) return;
    int cnt = EPW;
    if (gbase + EPW > E) cnt = (int)(E - gbase);

    const uint2* xf2 = (const uint2*)g_XF;   // 8B = 4 halves per lane
    const unsigned un = (unsigned)n;

    float4 acc = make_float4(0.f, 0.f, 0.f, 0.f);
    int prev = s_dst[i0];

    #pragma unroll 4
    for (int i = 0; i < cnt; i++) {
        const int idx  = i0 + i;
        const int s    = s_src[idx];
        const int d    = s_dst[idx];
        const float wv = s_w[idx];

        if (d != prev) {                         // warp-uniform branch
            if ((unsigned)prev < un) {
                float* p = &out[prev * NFEAT + lane * 4];
                atomicAdd(p + 0, acc.x);
                atomicAdd(p + 1, acc.y);
                atomicAdd(p + 2, acc.z);
                atomicAdd(p + 3, acc.w);
            }
            acc = make_float4(0.f, 0.f, 0.f, 0.f);
            prev = d;
        }
        if ((unsigned)s < un) {
            uint2 u = __ldg(&xf2[s * 32 + lane]);    // 256B coalesced per warp
            __half2 h0 = *reinterpret_cast<__half2*>(&u.x);
            __half2 h1 = *reinterpret_cast<__half2*>(&u.y);
            float2 f0 = __half22float2(h0);
            float2 f1 = __half22float2(h1);
            acc.x += wv * f0.x;
            acc.y += wv * f0.y;
            acc.z += wv * f1.x;
            acc.w += wv * f1.y;
        }
    }
    if ((unsigned)prev < un) {
        float* p = &out[prev * NFEAT + lane * 4];
        atomicAdd(p + 0, acc.x);
        atomicAdd(p + 1, acc.y);
        atomicAdd(p + 2, acc.z);
        atomicAdd(p + 3, acc.w);
    }
}

// ---------------------------------------------------------------------------
// Launch (kernel launches only — graph-capturable)
// ---------------------------------------------------------------------------
extern "C" void kernel_launch(void* const* d_in, const int* in_sizes, int n_in,
                              void* d_out, int out_size) {
    const float* x    = (const float*)d_in[0];   // [n, 128] fp32
    const float* filt = (const float*)d_in[1];   // [128, 128] fp32
    const int*   src  = (const int*)d_in[2];     // [E] int32
    const int*   dst  = (const int*)d_in[3];     // [E] int32, sorted
    const float* w    = (const float*)d_in[4];   // [E] fp32
    float*       out  = (float*)d_out;           // [n, 128] fp32

    const int n = in_sizes[0] / NFEAT;   // 100000
    const int E = in_sizes[2];           // 3200000

    // Prep: zero out + split filters into bf16 hi/lo (transposed)
    prep_kernel<<<2048, 256>>>(filt, (float4*)out, out_size / 4);

    // GEMM: XF = x @ F via mma.sync bf16 3-term split (fp16 epilogue)
    dim3 ggrid((n + 127) / 128, 2);
    gemm_mma_kernel<<<ggrid, 256>>>(x, n);

    // Sorted-segment aggregation (fp16 gather, fp32 accumulate)
    int agg_blocks = (E + EPB - 1) / EPB;
    aggregate_kernel<<<agg_blocks, 256>>>(src, dst, w, out, E, n);
}